// round 12
// baseline (speedup 1.0000x reference)
#include <cuda_runtime.h>
#include <cstdint>
#include <math.h>

typedef unsigned long long ull;

#define BB 64
#define SS 512
#define EE 256
#define HH 512
#define GG 2048
#define BSH (BB*SS*HH)
#define NBLK 128

// scan smem layout (float offsets) — identical to R4 (best proven: 5215us)
#define SW_OFF 0            // [40][514] weights
#define X_OFF  20576        // 2 slots x (xh[32][130] + xc[32][130])
#define SLOT   8320
#define XC_OFF 4160
#define RED_OFF 20576       // overlaps X slots (used after all tiles consumed)
#define SMEM_FLOATS 37216
#define SCAN_SMEM (SMEM_FLOATS*4)

__device__ float g_uproj[BB*SS*GG];
__device__ float g_h[2][BB*HH];
__device__ float g_c[2][BB*HH];
__device__ unsigned int g_ctr;

// ---------------- helpers ----------------
__device__ __forceinline__ void ffma2(ull& d, ull a, ull b) {
    asm("fma.rn.f32x2 %0, %1, %2, %0;" : "+l"(d) : "l"(a), "l"(b));
}
__device__ __forceinline__ ull dup2(float a) {
    ull r; asm("mov.b64 %0, {%1,%1};" : "=l"(r) : "f"(a)); return r;
}
__device__ __forceinline__ float fold2(ull v) {
    float lo, hi;
    asm("mov.b64 {%0,%1}, %2;" : "=f"(lo), "=f"(hi) : "l"(v));
    return lo + hi;
}
__device__ __forceinline__ float sigf(float x) { return 1.0f / (1.0f + expf(-x)); }

// ---------------- init ----------------
__global__ void init_state() {
    int i = blockIdx.x * 256 + threadIdx.x;  // 32768
    g_h[0][i] = 0.f;
    g_c[0][i] = 0.f;
    if (i == 0) g_ctr = 0u;
}

// ---------------- u_proj GEMM (FFMA2, proven) ----------------
__global__ void __launch_bounds__(256) gemm_uproj(
    const float* __restrict__ A, const float* __restrict__ W, const float* __restrict__ bias)
{
    __shared__ float As[8][132];
    __shared__ float Bs[8][132];
    const int tid = threadIdx.x;
    const int bm = blockIdx.y * 128, bn = blockIdx.x * 128;
    const int tx = tid & 15, ty = tid >> 4;
    const int lrow = tid >> 1, lk = (tid & 1) * 4;
    const float* Aptr = A + (size_t)(bm + lrow) * EE + lk;
    const float* Wptr = W + (size_t)(bn + lrow) * EE + lk;

    ull acc2[8][4];
#pragma unroll
    for (int r = 0; r < 8; r++)
#pragma unroll
        for (int c = 0; c < 4; c++) acc2[r][c] = 0ull;

    float4 av = *(const float4*)(Aptr);
    float4 bv = *(const float4*)(Wptr);

    for (int k0 = 0; k0 < EE; k0 += 8) {
        __syncthreads();
        As[lk+0][lrow]=av.x; As[lk+1][lrow]=av.y; As[lk+2][lrow]=av.z; As[lk+3][lrow]=av.w;
        Bs[lk+0][lrow]=bv.x; Bs[lk+1][lrow]=bv.y; Bs[lk+2][lrow]=bv.z; Bs[lk+3][lrow]=bv.w;
        __syncthreads();
        if (k0 + 8 < EE) { av = *(const float4*)(Aptr+k0+8); bv = *(const float4*)(Wptr+k0+8); }
#pragma unroll
        for (int kk = 0; kk < 8; kk++) {
            float4 a0 = *(const float4*)&As[kk][ty*8];
            float4 a1 = *(const float4*)&As[kk][ty*8+4];
            ulonglong2 b0 = *(const ulonglong2*)&Bs[kk][tx*8];
            ulonglong2 b1 = *(const ulonglong2*)&Bs[kk][tx*8+4];
            float ar[8] = {a0.x,a0.y,a0.z,a0.w,a1.x,a1.y,a1.z,a1.w};
            ull br2[4] = {b0.x, b0.y, b1.x, b1.y};
#pragma unroll
            for (int r = 0; r < 8; r++) {
                ull ad = dup2(ar[r]);
#pragma unroll
                for (int c = 0; c < 4; c++) ffma2(acc2[r][c], ad, br2[c]);
            }
        }
    }

    float bsr[8];
#pragma unroll
    for (int c = 0; c < 8; c++) bsr[c] = bias[bn + tx*8 + c];
#pragma unroll
    for (int r = 0; r < 8; r++) {
        float accv[8];
#pragma unroll
        for (int c = 0; c < 4; c++) {
            float lo, hi;
            asm("mov.b64 {%0,%1}, %2;" : "=f"(lo), "=f"(hi) : "l"(acc2[r][c]));
            accv[2*c] = lo; accv[2*c+1] = hi;
        }
        float* cp = g_uproj + (size_t)(bm + ty*8 + r) * GG + bn + tx*8;
        float4 o0 = {accv[0]+bsr[0], accv[1]+bsr[1], accv[2]+bsr[2], accv[3]+bsr[3]};
        float4 o1 = {accv[4]+bsr[4], accv[5]+bsr[5], accv[6]+bsr[6], accv[7]+bsr[7]};
        *(float4*)(cp) = o0; *(float4*)(cp + 4) = o1;
    }
}

// ---------------- persistent scan: R4 layout, 512 threads (16 warps) ----------------
// Block: jg = bid>>1 (8 j), bg = bid&1 (32 b). Rows 0..39 = gate*8+jj (f,i,o,cT,wd).
// Warp w (0..15): rg = w&7 (rows rg*5..+4), khalf = w>>3. Lane: ksub = lane>>3, cg = lane&7.
// k-slice = (khalf*4+ksub)*16 per 128-tile; cols cg + 8*ci.
__global__ void __launch_bounds__(512, 1) lstm_scan(
    const float* __restrict__ ts,
    const float* __restrict__ Wall,
    const float* __restrict__ ball,
    const float* __restrict__ Wd,
    const float* __restrict__ bd,
    float* __restrict__ out)
{
    extern __shared__ float sm[];
    const int tid = threadIdx.x;
    const int bid = blockIdx.x;
    const int jbase = (bid >> 1) * 8;
    const int bbase = (bid & 1) * 32;

    // ---- weights -> smem (stride 514), once ----
    for (int idx = tid; idx < 40*512; idx += 512) {
        int row = idx >> 9, k = idx & 511;
        int t = row >> 3, jr = jbase + (row & 7);
        float v = (t < 4) ? __ldg(Wall + (size_t)(t*512 + jr)*512 + k)
                          : __ldg(Wd + (size_t)jr*512 + k);
        sm[SW_OFF + row*514 + k] = v;
    }

    // compute identity
    const int w    = tid >> 5;
    const int lane = tid & 31;
    const int rg   = w & 7;            // 8 row-groups of 5 rows
    const int khalf= w >> 3;           // k half
    const int ksub = lane >> 3;
    const int cg   = lane & 7;
    const int ks16 = (khalf*4 + ksub) * 16;

    // staging identity: 16 threads per x row
    const int sb = tid >> 4;           // row 0..31
    const int ss = tid & 15;           // chunk phase

    // phase-B identity (threads 0..255 only)
    const int pb = tid >> 3;
    const int pj = tid & 7;
    const int b2 = bbase + (pb & 31);
    const int j  = jbase + pj;
    const float bfb = __ldg(ball + j);
    const float bib = __ldg(ball + 512 + j);
    const float bob = __ldg(ball + 1024 + j);
    const float bcb = __ldg(ball + 1536 + j);
    const float bdj = __ldg(bd + j);

    __syncthreads();

    for (int s = 0; s < SS; s++) {
        const float* hsrc = g_h[s & 1];
        const float* csrc = g_c[s & 1];

        // phase-B operand prefetch (threads 0..255)
        float u0 = 0.f, u1 = 0.f, u2 = 0.f, u3 = 0.f, tv = 0.f, c_old = 0.f;
        if (tid < 256) {
            const float* up = g_uproj + ((size_t)b2 * SS + s) * GG;
            u0 = __ldg(up + j);
            u1 = __ldg(up + 512 + j);
            u2 = __ldg(up + 1024 + j);
            u3 = __ldg(up + 1536 + j);
            tv = __ldg(ts + b2 * SS + s);
            c_old = __ldcg(csrc + b2 * HH + j);
        }

        float4 rh[2], rc[2];
        const float* hrow = hsrc + (size_t)(bbase + sb) * HH;
        const float* crow = csrc + (size_t)(bbase + sb) * HH;

        // preload tile 0, store, preload tile 1
#pragma unroll
        for (int u = 0; u < 2; u++) {
            rh[u] = __ldcg((const float4*)(hrow + (ss + 16*u) * 4));
            rc[u] = __ldcg((const float4*)(crow + (ss + 16*u) * 4));
        }
        {
            float* dh = sm + X_OFF + sb*130;
            float* dc = dh + XC_OFF;
#pragma unroll
            for (int u = 0; u < 2; u++) {
                int o = (ss + 16*u) * 4;
                *(float2*)(dh + o)     = make_float2(rh[u].x, rh[u].y);
                *(float2*)(dh + o + 2) = make_float2(rh[u].z, rh[u].w);
                *(float2*)(dc + o)     = make_float2(rc[u].x, rc[u].y);
                *(float2*)(dc + o + 2) = make_float2(rc[u].z, rc[u].w);
            }
        }
#pragma unroll
        for (int u = 0; u < 2; u++) {
            rh[u] = __ldcg((const float4*)(hrow + 128 + (ss + 16*u) * 4));
            rc[u] = __ldcg((const float4*)(crow + 128 + (ss + 16*u) * 4));
        }
        __syncthreads();

        ull acc[5][4];
#pragma unroll
        for (int rl = 0; rl < 5; rl++)
#pragma unroll
            for (int i = 0; i < 4; i++) acc[rl][i] = 0ull;

#pragma unroll 1
        for (int t = 0; t < 4; t++) {
            const float* xb = sm + X_OFF + (t & 1) * SLOT + cg * 130 + ks16;
            const float* wb = sm + SW_OFF + (rg*5) * 514 + t * 128 + ks16;
            if (rg < 6) {
#pragma unroll
                for (int kk = 0; kk < 8; kk++) {
                    ull x0 = *(const ull*)(xb + 2*kk);
                    ull x1 = *(const ull*)(xb + 1040 + 2*kk);
                    ull x2 = *(const ull*)(xb + 2080 + 2*kk);
                    ull x3 = *(const ull*)(xb + 3120 + 2*kk);
#pragma unroll
                    for (int rl = 0; rl < 5; rl++) {
                        ull wv = *(const ull*)(wb + rl*514 + 2*kk);
                        ffma2(acc[rl][0], wv, x0);
                        ffma2(acc[rl][1], wv, x1);
                        ffma2(acc[rl][2], wv, x2);
                        ffma2(acc[rl][3], wv, x3);
                    }
                }
            } else if (rg == 6) {
                const float* xcb = xb + XC_OFF;
#pragma unroll
                for (int kk = 0; kk < 8; kk++) {
                    ull h0 = *(const ull*)(xb + 2*kk);
                    ull h1 = *(const ull*)(xb + 1040 + 2*kk);
                    ull h2 = *(const ull*)(xb + 2080 + 2*kk);
                    ull h3 = *(const ull*)(xb + 3120 + 2*kk);
                    ull c0 = *(const ull*)(xcb + 2*kk);
                    ull c1 = *(const ull*)(xcb + 1040 + 2*kk);
                    ull c2 = *(const ull*)(xcb + 2080 + 2*kk);
                    ull c3 = *(const ull*)(xcb + 3120 + 2*kk);
#pragma unroll
                    for (int rl = 0; rl < 2; rl++) {   // rows 30,31 (cT j6,7): h
                        ull wv = *(const ull*)(wb + rl*514 + 2*kk);
                        ffma2(acc[rl][0], wv, h0);
                        ffma2(acc[rl][1], wv, h1);
                        ffma2(acc[rl][2], wv, h2);
                        ffma2(acc[rl][3], wv, h3);
                    }
#pragma unroll
                    for (int rl = 2; rl < 5; rl++) {   // rows 32-34 (W_d): c
                        ull wv = *(const ull*)(wb + rl*514 + 2*kk);
                        ffma2(acc[rl][0], wv, c0);
                        ffma2(acc[rl][1], wv, c1);
                        ffma2(acc[rl][2], wv, c2);
                        ffma2(acc[rl][3], wv, c3);
                    }
                }
            } else {
                const float* xcb = xb + XC_OFF;
#pragma unroll
                for (int kk = 0; kk < 8; kk++) {
                    ull c0 = *(const ull*)(xcb + 2*kk);
                    ull c1 = *(const ull*)(xcb + 1040 + 2*kk);
                    ull c2 = *(const ull*)(xcb + 2080 + 2*kk);
                    ull c3 = *(const ull*)(xcb + 3120 + 2*kk);
#pragma unroll
                    for (int rl = 0; rl < 5; rl++) {   // rows 35-39 (W_d): c
                        ull wv = *(const ull*)(wb + rl*514 + 2*kk);
                        ffma2(acc[rl][0], wv, c0);
                        ffma2(acc[rl][1], wv, c1);
                        ffma2(acc[rl][2], wv, c2);
                        ffma2(acc[rl][3], wv, c3);
                    }
                }
            }
            if (t < 3) {
                float* dh = sm + X_OFF + ((t + 1) & 1) * SLOT + sb*130;
                float* dc = dh + XC_OFF;
#pragma unroll
                for (int u = 0; u < 2; u++) {
                    int o = (ss + 16*u) * 4;
                    *(float2*)(dh + o)     = make_float2(rh[u].x, rh[u].y);
                    *(float2*)(dh + o + 2) = make_float2(rh[u].z, rh[u].w);
                    *(float2*)(dc + o)     = make_float2(rc[u].x, rc[u].y);
                    *(float2*)(dc + o + 2) = make_float2(rc[u].z, rc[u].w);
                }
                if (t < 2) {
                    int tb = (t + 2) * 128;
#pragma unroll
                    for (int u = 0; u < 2; u++) {
                        rh[u] = __ldcg((const float4*)(hrow + tb + (ss + 16*u) * 4));
                        rc[u] = __ldcg((const float4*)(crow + tb + (ss + 16*u) * 4));
                    }
                }
            }
            __syncthreads();
        }

        // ---- block-local reduction: partials -> smem (overlaps x slots) ----
        {
            const int ksl = khalf*4 + ksub;
#pragma unroll
            for (int rl = 0; rl < 5; rl++) {
                int row = rg*5 + rl;
#pragma unroll
                for (int i = 0; i < 4; i++) {
                    int bbx = cg + 8*i;
                    sm[RED_OFF + ((row*32 + bbx) << 3) + ksl] = fold2(acc[rl][i]);
                }
            }
        }
        __syncthreads();

        // ---- phase B (threads 0..255) ----
        if (tid < 256) {
            float p[5];
#pragma unroll
            for (int t = 0; t < 5; t++) {
                const float4* r0 = (const float4*)(sm + RED_OFF + (((t*8 + pj)*32 + (pb & 31)) << 3));
                float4 a = r0[0], bq = r0[1];
                p[t] = ((a.x + a.y) + (a.z + a.w)) + ((bq.x + bq.y) + (bq.z + bq.w));
            }
            float dec  = 1.0f / logf(2.718281828459045f + tv);
            float cs1  = tanhf(p[4] + bdj);
            float cadj = (c_old - cs1) + cs1 * dec;
            float f  = sigf(p[0] + bfb + u0);
            float ii = sigf(p[1] + bib + u1);
            float o  = sigf(p[2] + bob + u2);
            float ct = tanhf(p[3] + bcb + u3);
            float cn = f * cadj + ii * ct;
            float hn = o * tanhf(cn);

            const int nb = (s + 1) & 1;
            const int ij = b2 * HH + j;
            g_h[nb][ij] = hn;
            g_c[nb][ij] = cn;
            out[((size_t)b2 * SS + s) * HH + j] = hn;
            if (s == SS - 1) {
                out[BSH + ij] = hn;
                out[BSH + BB * HH + ij] = cn;
            }
        }

        // ---- grid barrier (R4 original) ----
        if (s < SS - 1) {
            __threadfence();
            __syncthreads();
            if (tid == 0) {
                atomicAdd(&g_ctr, 1u);
                unsigned tgt = (unsigned)(s + 1) * NBLK;
                volatile unsigned* pc = &g_ctr;
                while (*pc < tgt) { }
            }
            __syncthreads();
        }
    }
}

extern "C" void kernel_launch(void* const* d_in, const int* in_sizes, int n_in,
                              void* d_out, int out_size) {
    const float* inputs = (const float*)d_in[0];
    const float* tstamp = (const float*)d_in[1];
    const float* Wall   = (const float*)d_in[2];
    const float* ball   = (const float*)d_in[3];
    const float* Uall   = (const float*)d_in[4];
    const float* uball  = (const float*)d_in[5];
    const float* Wd     = (const float*)d_in[6];
    const float* bd     = (const float*)d_in[7];
    float* out = (float*)d_out;

    cudaFuncSetAttribute(lstm_scan, cudaFuncAttributeMaxDynamicSharedMemorySize, SCAN_SMEM);

    init_state<<<128, 256>>>();
    dim3 g1(GG / 128, (BB * SS) / 128);
    gemm_uproj<<<g1, 256>>>(inputs, Uall, uball);
    lstm_scan<<<NBLK, 512, SCAN_SMEM>>>(tstamp, Wall, ball, Wd, bd, out);
}

// round 13
// speedup vs baseline: 1.1759x; 1.1759x over previous
#include <cuda_runtime.h>
#include <cstdint>
#include <math.h>

typedef unsigned long long ull;

#define BB 64
#define SS 512
#define EE 256
#define HH 512
#define GG 2048
#define BSH (BB*SS*HH)
#define NBLK 128

// scan smem layout (float offsets) — identical to R4 (best proven: 5215us)
#define SW_OFF 0            // [40][514] weights
#define X_OFF  20576        // 2 slots x (xh[32][130] + xc[32][130])
#define SLOT   8320
#define XC_OFF 4160
#define RED_OFF 20576       // overlaps X slots (used after all tiles consumed)
#define SMEM_FLOATS 37216
#define SCAN_SMEM (SMEM_FLOATS*4)

__device__ float g_uproj[BB*SS*GG];
__device__ float g_h[2][BB*HH];
__device__ float g_c[2][BB*HH];
__device__ unsigned int g_ctr;

// ---------------- helpers ----------------
__device__ __forceinline__ void ffma2(ull& d, ull a, ull b) {
    asm("fma.rn.f32x2 %0, %1, %2, %0;" : "+l"(d) : "l"(a), "l"(b));
}
__device__ __forceinline__ ull dup2(float a) {
    ull r; asm("mov.b64 %0, {%1,%1};" : "=l"(r) : "f"(a)); return r;
}
__device__ __forceinline__ float fold2(ull v) {
    float lo, hi;
    asm("mov.b64 {%0,%1}, %2;" : "=f"(lo), "=f"(hi) : "l"(v));
    return lo + hi;
}
__device__ __forceinline__ float sigf(float x) { return 1.0f / (1.0f + expf(-x)); }

// ---------------- u_proj GEMM fused with state init (2-launch stream) ----------------
__global__ void __launch_bounds__(256) gemm_uproj_init(
    const float* __restrict__ A, const float* __restrict__ W, const float* __restrict__ bias)
{
    __shared__ float As[8][132];
    __shared__ float Bs[8][132];
    const int tid = threadIdx.x;

    // fused init: first 128 (of 4096) blocks zero h0/c0 and the barrier counter.
    // Disjoint from uproj outputs; scan launch observes all of it.
    {
        const int flat = blockIdx.y * gridDim.x + blockIdx.x;
        if (flat < 128) {
            int i = flat * 256 + tid;     // 32768 total
            g_h[0][i] = 0.f;
            g_c[0][i] = 0.f;
            if (i == 0) g_ctr = 0u;
        }
    }

    const int bm = blockIdx.y * 128, bn = blockIdx.x * 128;
    const int tx = tid & 15, ty = tid >> 4;
    const int lrow = tid >> 1, lk = (tid & 1) * 4;
    const float* Aptr = A + (size_t)(bm + lrow) * EE + lk;
    const float* Wptr = W + (size_t)(bn + lrow) * EE + lk;

    ull acc2[8][4];
#pragma unroll
    for (int r = 0; r < 8; r++)
#pragma unroll
        for (int c = 0; c < 4; c++) acc2[r][c] = 0ull;

    float4 av = *(const float4*)(Aptr);
    float4 bv = *(const float4*)(Wptr);

    for (int k0 = 0; k0 < EE; k0 += 8) {
        __syncthreads();
        As[lk+0][lrow]=av.x; As[lk+1][lrow]=av.y; As[lk+2][lrow]=av.z; As[lk+3][lrow]=av.w;
        Bs[lk+0][lrow]=bv.x; Bs[lk+1][lrow]=bv.y; Bs[lk+2][lrow]=bv.z; Bs[lk+3][lrow]=bv.w;
        __syncthreads();
        if (k0 + 8 < EE) { av = *(const float4*)(Aptr+k0+8); bv = *(const float4*)(Wptr+k0+8); }
#pragma unroll
        for (int kk = 0; kk < 8; kk++) {
            float4 a0 = *(const float4*)&As[kk][ty*8];
            float4 a1 = *(const float4*)&As[kk][ty*8+4];
            ulonglong2 b0 = *(const ulonglong2*)&Bs[kk][tx*8];
            ulonglong2 b1 = *(const ulonglong2*)&Bs[kk][tx*8+4];
            float ar[8] = {a0.x,a0.y,a0.z,a0.w,a1.x,a1.y,a1.z,a1.w};
            ull br2[4] = {b0.x, b0.y, b1.x, b1.y};
#pragma unroll
            for (int r = 0; r < 8; r++) {
                ull ad = dup2(ar[r]);
#pragma unroll
                for (int c = 0; c < 4; c++) ffma2(acc2[r][c], ad, br2[c]);
            }
        }
    }

    float bsr[8];
#pragma unroll
    for (int c = 0; c < 8; c++) bsr[c] = bias[bn + tx*8 + c];
#pragma unroll
    for (int r = 0; r < 8; r++) {
        float accv[8];
#pragma unroll
        for (int c = 0; c < 4; c++) {
            float lo, hi;
            asm("mov.b64 {%0,%1}, %2;" : "=f"(lo), "=f"(hi) : "l"(acc2[r][c]));
            accv[2*c] = lo; accv[2*c+1] = hi;
        }
        float* cp = g_uproj + (size_t)(bm + ty*8 + r) * GG + bn + tx*8;
        float4 o0 = {accv[0]+bsr[0], accv[1]+bsr[1], accv[2]+bsr[2], accv[3]+bsr[3]};
        float4 o1 = {accv[4]+bsr[4], accv[5]+bsr[5], accv[6]+bsr[6], accv[7]+bsr[7]};
        *(float4*)(cp) = o0; *(float4*)(cp + 4) = o1;
    }
}

// ---------------- persistent scan: EXACT R4 body (5215us champion) ----------------
__global__ void __launch_bounds__(256, 1) lstm_scan(
    const float* __restrict__ ts,
    const float* __restrict__ Wall,
    const float* __restrict__ ball,
    const float* __restrict__ Wd,
    const float* __restrict__ bd,
    float* __restrict__ out)
{
    extern __shared__ float sm[];
    const int tid = threadIdx.x;
    const int bid = blockIdx.x;
    const int jbase = (bid >> 1) * 8;
    const int bbase = (bid & 1) * 32;

    // ---- weights -> smem (stride 514), once ----
    for (int idx = tid; idx < 40*512; idx += 256) {
        int row = idx >> 9, k = idx & 511;
        int t = row >> 3, jr = jbase + (row & 7);
        float v = (t < 4) ? __ldg(Wall + (size_t)(t*512 + jr)*512 + k)
                          : __ldg(Wd + (size_t)jr*512 + k);
        sm[SW_OFF + row*514 + k] = v;
    }

    // compute identity
    const int w    = tid >> 5;
    const int lane = tid & 31;
    const int rg   = w & 3;
    const int khalf= w >> 2;
    const int ksub = lane >> 3;
    const int cg   = lane & 7;
    const int ks16 = (khalf*4 + ksub) * 16;

    // staging identity
    const int sb = tid >> 3;
    const int ss = tid & 7;

    // phase-B identity
    const int pb = tid >> 3;
    const int pj = tid & 7;
    const int b2 = bbase + pb;
    const int j  = jbase + pj;
    const float bfb = __ldg(ball + j);
    const float bib = __ldg(ball + 512 + j);
    const float bob = __ldg(ball + 1024 + j);
    const float bcb = __ldg(ball + 1536 + j);
    const float bdj = __ldg(bd + j);

    __syncthreads();

    for (int s = 0; s < SS; s++) {
        const float* hsrc = g_h[s & 1];
        const float* csrc = g_c[s & 1];

        // phase-B operand prefetch
        const float* up = g_uproj + ((size_t)b2 * SS + s) * GG;
        float u0 = __ldg(up + j);
        float u1 = __ldg(up + 512 + j);
        float u2 = __ldg(up + 1024 + j);
        float u3 = __ldg(up + 1536 + j);
        float tv = __ldg(ts + b2 * SS + s);
        float c_old = __ldcg(csrc + b2 * HH + j);

        float4 rh[4], rc[4];
        const float* hrow = hsrc + (size_t)(bbase + sb) * HH;
        const float* crow = csrc + (size_t)(bbase + sb) * HH;

        // preload tile 0, store, preload tile 1
#pragma unroll
        for (int u = 0; u < 4; u++) {
            rh[u] = __ldcg((const float4*)(hrow + (ss + 8*u) * 4));
            rc[u] = __ldcg((const float4*)(crow + (ss + 8*u) * 4));
        }
        {
            float* dh = sm + X_OFF + sb*130;
            float* dc = dh + XC_OFF;
#pragma unroll
            for (int u = 0; u < 4; u++) {
                int o = (ss + 8*u) * 4;
                *(float2*)(dh + o)     = make_float2(rh[u].x, rh[u].y);
                *(float2*)(dh + o + 2) = make_float2(rh[u].z, rh[u].w);
                *(float2*)(dc + o)     = make_float2(rc[u].x, rc[u].y);
                *(float2*)(dc + o + 2) = make_float2(rc[u].z, rc[u].w);
            }
        }
#pragma unroll
        for (int u = 0; u < 4; u++) {
            rh[u] = __ldcg((const float4*)(hrow + 128 + (ss + 8*u) * 4));
            rc[u] = __ldcg((const float4*)(crow + 128 + (ss + 8*u) * 4));
        }
        __syncthreads();

        ull acc[10][4];
#pragma unroll
        for (int rl = 0; rl < 10; rl++)
#pragma unroll
            for (int i = 0; i < 4; i++) acc[rl][i] = 0ull;

#pragma unroll 1
        for (int t = 0; t < 4; t++) {
            const float* xb = sm + X_OFF + (t & 1) * SLOT + cg * 130 + ks16;
            const float* wb = sm + SW_OFF + rg * 10 * 514 + t * 128 + ks16;
            if (rg < 3) {
#pragma unroll
                for (int kk = 0; kk < 8; kk++) {
                    ull x0 = *(const ull*)(xb + 2*kk);
                    ull x1 = *(const ull*)(xb + 1040 + 2*kk);
                    ull x2 = *(const ull*)(xb + 2080 + 2*kk);
                    ull x3 = *(const ull*)(xb + 3120 + 2*kk);
#pragma unroll
                    for (int rl = 0; rl < 10; rl++) {
                        ull wv = *(const ull*)(wb + rl*514 + 2*kk);
                        ffma2(acc[rl][0], wv, x0);
                        ffma2(acc[rl][1], wv, x1);
                        ffma2(acc[rl][2], wv, x2);
                        ffma2(acc[rl][3], wv, x3);
                    }
                }
            } else {
                const float* xcb = xb + XC_OFF;
#pragma unroll
                for (int kk = 0; kk < 8; kk++) {
                    ull h0 = *(const ull*)(xb + 2*kk);
                    ull h1 = *(const ull*)(xb + 1040 + 2*kk);
                    ull h2 = *(const ull*)(xb + 2080 + 2*kk);
                    ull h3 = *(const ull*)(xb + 3120 + 2*kk);
                    ull c0 = *(const ull*)(xcb + 2*kk);
                    ull c1 = *(const ull*)(xcb + 1040 + 2*kk);
                    ull c2 = *(const ull*)(xcb + 2080 + 2*kk);
                    ull c3 = *(const ull*)(xcb + 3120 + 2*kk);
#pragma unroll
                    for (int rl = 0; rl < 2; rl++) {
                        ull wv = *(const ull*)(wb + rl*514 + 2*kk);
                        ffma2(acc[rl][0], wv, h0);
                        ffma2(acc[rl][1], wv, h1);
                        ffma2(acc[rl][2], wv, h2);
                        ffma2(acc[rl][3], wv, h3);
                    }
#pragma unroll
                    for (int rl = 2; rl < 10; rl++) {
                        ull wv = *(const ull*)(wb + rl*514 + 2*kk);
                        ffma2(acc[rl][0], wv, c0);
                        ffma2(acc[rl][1], wv, c1);
                        ffma2(acc[rl][2], wv, c2);
                        ffma2(acc[rl][3], wv, c3);
                    }
                }
            }
            if (t < 3) {
                float* dh = sm + X_OFF + ((t + 1) & 1) * SLOT + sb*130;
                float* dc = dh + XC_OFF;
#pragma unroll
                for (int u = 0; u < 4; u++) {
                    int o = (ss + 8*u) * 4;
                    *(float2*)(dh + o)     = make_float2(rh[u].x, rh[u].y);
                    *(float2*)(dh + o + 2) = make_float2(rh[u].z, rh[u].w);
                    *(float2*)(dc + o)     = make_float2(rc[u].x, rc[u].y);
                    *(float2*)(dc + o + 2) = make_float2(rc[u].z, rc[u].w);
                }
                if (t < 2) {
                    int tb = (t + 2) * 128;
#pragma unroll
                    for (int u = 0; u < 4; u++) {
                        rh[u] = __ldcg((const float4*)(hrow + tb + (ss + 8*u) * 4));
                        rc[u] = __ldcg((const float4*)(crow + tb + (ss + 8*u) * 4));
                    }
                }
            }
            __syncthreads();
        }

        // ---- block-local reduction: partials -> smem (overlaps x slots) ----
        {
            const int ksl = khalf*4 + ksub;
#pragma unroll
            for (int rl = 0; rl < 10; rl++) {
                int row = rg*10 + rl;
#pragma unroll
                for (int i = 0; i < 4; i++) {
                    int bbx = cg + 8*i;
                    sm[RED_OFF + ((row*32 + bbx) << 3) + ksl] = fold2(acc[rl][i]);
                }
            }
        }
        __syncthreads();

        // ---- phase B ----
        {
            float p[5];
#pragma unroll
            for (int t = 0; t < 5; t++) {
                const float4* r0 = (const float4*)(sm + RED_OFF + (((t*8 + pj)*32 + pb) << 3));
                float4 a = r0[0], bq = r0[1];
                p[t] = ((a.x + a.y) + (a.z + a.w)) + ((bq.x + bq.y) + (bq.z + bq.w));
            }
            float dec  = 1.0f / logf(2.718281828459045f + tv);
            float cs1  = tanhf(p[4] + bdj);
            float cadj = (c_old - cs1) + cs1 * dec;
            float f  = sigf(p[0] + bfb + u0);
            float ii = sigf(p[1] + bib + u1);
            float o  = sigf(p[2] + bob + u2);
            float ct = tanhf(p[3] + bcb + u3);
            float cn = f * cadj + ii * ct;
            float hn = o * tanhf(cn);

            const int nb = (s + 1) & 1;
            const int ij = b2 * HH + j;
            g_h[nb][ij] = hn;
            g_c[nb][ij] = cn;
            out[((size_t)b2 * SS + s) * HH + j] = hn;
            if (s == SS - 1) {
                out[BSH + ij] = hn;
                out[BSH + BB * HH + ij] = cn;
            }
        }

        // ---- grid barrier (R4 original) ----
        if (s < SS - 1) {
            __threadfence();
            __syncthreads();
            if (tid == 0) {
                atomicAdd(&g_ctr, 1u);
                unsigned tgt = (unsigned)(s + 1) * NBLK;
                volatile unsigned* pc = &g_ctr;
                while (*pc < tgt) { }
            }
            __syncthreads();
        }
    }
}

extern "C" void kernel_launch(void* const* d_in, const int* in_sizes, int n_in,
                              void* d_out, int out_size) {
    const float* inputs = (const float*)d_in[0];
    const float* tstamp = (const float*)d_in[1];
    const float* Wall   = (const float*)d_in[2];
    const float* ball   = (const float*)d_in[3];
    const float* Uall   = (const float*)d_in[4];
    const float* uball  = (const float*)d_in[5];
    const float* Wd     = (const float*)d_in[6];
    const float* bd     = (const float*)d_in[7];
    float* out = (float*)d_out;

    cudaFuncSetAttribute(lstm_scan, cudaFuncAttributeMaxDynamicSharedMemorySize, SCAN_SMEM);

    dim3 g1(GG / 128, (BB * SS) / 128);
    gemm_uproj_init<<<g1, 256>>>(inputs, Uall, uball);
    lstm_scan<<<NBLK, 256, SCAN_SMEM>>>(tstamp, Wall, ball, Wd, bd, out);
}